// round 9
// baseline (speedup 1.0000x reference)
#include <cuda_runtime.h>
#include <math.h>

#define B_   128
#define S_   512
#define IN_  128
#define H_   512
#define C_   1000
#define WSP2 68           // Ws row pitch (floats): 16B-aligned, bank-staggered
#define HP2  68           // per-warp Hs row pitch (floats)

// smem: Ws [512][WSP2] + Hs 8x[8][HP2] + Pr [8][512]
#define SMEM_RNN ((512 * WSP2 + 8 * 8 * HP2 + 8 * 512) * 4)

// Scratch (device globals: allocation-free per harness rules)
__device__ float g_xp [(size_t)B_ * S_ * H_];   // input projection (both layers)
__device__ float g_seq[(size_t)B_ * S_ * H_];   // layer-0 hidden sequence
__device__ float g_h  [2 * B_ * H_];            // double-buffered hidden state

// ---------------- packed fp32x2 helpers (SASS FFMA2 path) -------------------
__device__ __forceinline__ unsigned long long pack2(float lo, float hi) {
    unsigned long long d;
    asm("mov.b64 %0, {%1, %2};" : "=l"(d)
        : "r"(__float_as_uint(lo)), "r"(__float_as_uint(hi)));
    return d;
}
__device__ __forceinline__ unsigned long long ffma2(
    unsigned long long a, unsigned long long b, unsigned long long c) {
    unsigned long long d;
    asm("fma.rn.f32x2 %0, %1, %2, %3;" : "=l"(d) : "l"(a), "l"(b), "l"(c));
    return d;
}
__device__ __forceinline__ unsigned long long fadd2(
    unsigned long long a, unsigned long long b) {
    unsigned long long d;
    asm("add.rn.f32x2 %0, %1, %2;" : "=l"(d) : "l"(a), "l"(b));
    return d;
}
__device__ __forceinline__ float2 unpack2(unsigned long long v) {
    unsigned lo, hi;
    asm("mov.b64 {%0, %1}, %2;" : "=r"(lo), "=r"(hi) : "l"(v));
    return make_float2(__uint_as_float(lo), __uint_as_float(hi));
}

// ---------------------------------------------------------------------------
// Persistent RNN layer, cluster edition.
// Grid (16, 8), cluster (1, 8): the 8 blocks sharing blockIdx.x form one
// cluster and exchange h via L2, synchronized by HW cluster barriers
// (arrive = release, wait = acquire; wait also acts as the block barrier).
// Block tile: 8 rows x 64 cols. Whh slice [512][64] resident in smem all
// layer. Warp g owns k-slice [64g, 64g+64): stages its own 8x64 h region
// (syncwarp only), computes 4x4 microtile per thread with packed f32x2 FMAs.
// ---------------------------------------------------------------------------
__global__ void __launch_bounds__(256, 1) rnn_layer_kernel(
    const float* __restrict__ xp, const float* __restrict__ Wh,
    float* __restrict__ hA, float* __restrict__ hB,
    float* __restrict__ seqOut)
{
    extern __shared__ float sm[];
    float* Ws = sm;                      // [512][WSP2] k-major (139 KB)
    float* Hs = Ws + 512 * WSP2;         // 8 x [8][HP2] per-warp (17 KB)
    float* Pr = Hs + 8 * 8 * HP2;        // [8][512] packed partials (16 KB)

    const int tid  = threadIdx.x;
    const int m0   = blockIdx.x << 3;    // 16 m-tiles -> 128 rows
    const int n0   = blockIdx.y << 6;    // 8 n-tiles  -> 512 cols
    const int g    = tid >> 5;           // warp = K-group 0..7
    const int lane = tid & 31;
    const int r0   = (lane >> 4) << 2;   // rows r0..r0+3 (0 or 4)
    const int c0   = (lane & 15) << 2;   // cols c0..c0+3 (0..60)
    const int kbeg = g << 6;
    float* HsW = Hs + g * (8 * HP2);

    // Load Whh slice once: Ws[k][n], n in [n0, n0+64), k in [0,512).
    // Coalesced LDG.128 along k; staggered pitch avoids STS conflicts.
    for (int i = tid; i < 64 * 128; i += 256) {
        int n  = i >> 7;                 // 0..63
        int k4 = i & 127;                // 0..127
        float4 v = *reinterpret_cast<const float4*>(
            &Wh[(size_t)(n0 + n) * H_ + (k4 << 2)]);
        int k = k4 << 2;
        Ws[(k + 0) * WSP2 + n] = v.x;
        Ws[(k + 1) * WSP2 + n] = v.y;
        Ws[(k + 2) * WSP2 + n] = v.z;
        Ws[(k + 3) * WSP2 + n] = v.w;
    }
    __syncthreads();

    // Epilogue: thread owns 2 adjacent outputs (one f32x2)
    const int i0 = tid << 1;
    const int er = tid >> 5;             // 0..7
    const int ec = (tid & 31) << 1;      // even 0..62

    const float* xptr = xp + ((size_t)(m0 + er) * S_) * H_ + n0 + ec;
    float2 xv = __ldg(reinterpret_cast<const float2*>(xptr));   // t = 0

    for (int t = 0; t < S_; ++t) {
        const float* hp = (t & 1) ? hA : hB;
        float*       hn = (t & 1) ? hB : hA;

        float s0 = 0.f, s1 = 0.f;

        if (t > 0) {
            // Wait for every cluster CTA's step-(t-1) stores (acquire).
            asm volatile("barrier.cluster.wait.aligned;" ::: "memory");

            // Per-warp staging of own k-slice (8 rows x 64 k)
#pragma unroll
            for (int j = 0; j < 4; ++j) {
                int idx = lane + (j << 5);
                int r = idx >> 4, k4 = idx & 15;
                float4 v = __ldcg(reinterpret_cast<const float4*>(
                    &hp[(size_t)(m0 + r) * H_ + kbeg + (k4 << 2)]));
                *reinterpret_cast<float4*>(&HsW[r * HP2 + (k4 << 2)]) = v;
            }
            __syncwarp();

            unsigned long long a00 = 0, a01 = 0, a10 = 0, a11 = 0;
            unsigned long long a20 = 0, a21 = 0, a30 = 0, a31 = 0;

#pragma unroll 4
            for (int k4i = 0; k4i < 16; ++k4i) {
                const int kk = k4i << 2;
                float4 h0 = *reinterpret_cast<const float4*>(&HsW[(r0 + 0) * HP2 + kk]);
                float4 h1 = *reinterpret_cast<const float4*>(&HsW[(r0 + 1) * HP2 + kk]);
                float4 h2 = *reinterpret_cast<const float4*>(&HsW[(r0 + 2) * HP2 + kk]);
                float4 h3 = *reinterpret_cast<const float4*>(&HsW[(r0 + 3) * HP2 + kk]);
#define RNN_SUBK(s, C)                                                         \
                {                                                              \
                    const ulonglong2 w = *reinterpret_cast<const ulonglong2*>( \
                        &Ws[(kbeg + kk + s) * WSP2 + c0]);                     \
                    unsigned long long d;                                      \
                    d = pack2(h0.C, h0.C);                                     \
                    a00 = ffma2(d, w.x, a00); a01 = ffma2(d, w.y, a01);        \
                    d = pack2(h1.C, h1.C);                                     \
                    a10 = ffma2(d, w.x, a10); a11 = ffma2(d, w.y, a11);        \
                    d = pack2(h2.C, h2.C);                                     \
                    a20 = ffma2(d, w.x, a20); a21 = ffma2(d, w.y, a21);        \
                    d = pack2(h3.C, h3.C);                                     \
                    a30 = ffma2(d, w.x, a30); a31 = ffma2(d, w.y, a31);        \
                }
                RNN_SUBK(0, x)
                RNN_SUBK(1, y)
                RNN_SUBK(2, z)
                RNN_SUBK(3, w)
#undef RNN_SUBK
            }

            // Packed partials: Pr[g][row*64 + col]
            float* pg = &Pr[g << 9];
            *reinterpret_cast<ulonglong2*>(&pg[(r0 + 0) * 64 + c0]) = make_ulonglong2(a00, a01);
            *reinterpret_cast<ulonglong2*>(&pg[(r0 + 1) * 64 + c0]) = make_ulonglong2(a10, a11);
            *reinterpret_cast<ulonglong2*>(&pg[(r0 + 2) * 64 + c0]) = make_ulonglong2(a20, a21);
            *reinterpret_cast<ulonglong2*>(&pg[(r0 + 3) * 64 + c0]) = make_ulonglong2(a30, a31);
            __syncthreads();

            unsigned long long sp = 0;
#pragma unroll
            for (int gg = 0; gg < 8; ++gg)
                sp = fadd2(sp, *reinterpret_cast<const unsigned long long*>(
                                   &Pr[(gg << 9) + i0]));
            float2 sf = unpack2(sp);
            s0 = sf.x; s1 = sf.y;
            // Pr reuse next step is safe: each thread's reduce-loads precede
            // its arrive below; next step's stores come after the wait.
        }
        // t == 0: h_{-1}=0 -> output = tanh(xp)

        float2 o;
        o.x = tanhf(s0 + xv.x);
        o.y = tanhf(s1 + xv.y);
        __stcg(reinterpret_cast<float2*>(&hn[(size_t)(m0 + er) * H_ + n0 + ec]), o);
        if (seqOut)
            __stcg(reinterpret_cast<float2*>(
                &seqOut[((size_t)(m0 + er) * S_ + t) * H_ + n0 + ec]), o);

        if (t != S_ - 1) {
            // Prefetch next step's xp (independent; hides under barrier skew)
            xv = __ldg(reinterpret_cast<const float2*>(xptr + (size_t)(t + 1) * H_));
            // Release this step's h stores to the cluster.
            asm volatile("barrier.cluster.arrive.aligned;" ::: "memory");
        }
    }
}

// ---------------------------------------------------------------------------
// C[M,N] = A[M,K] @ W[N,K]^T + b1[N] + b2[N]
// 128x64 tile, BK=16, 256 threads, 8x4 microtile, packed f32x2 FMAs.
// ---------------------------------------------------------------------------
__global__ __launch_bounds__(256) void sgemm_bias(
    const float* __restrict__ A, const float* __restrict__ W,
    const float* __restrict__ b1, const float* __restrict__ b2,
    float* __restrict__ C, int M, int N, int K)
{
    __shared__ float As[16][132];
    __shared__ float Wt[16][68];
    const int tid = threadIdx.x;
    const int tx = tid & 15, ty = tid >> 4;
    const int m0 = blockIdx.x * 128, n0 = blockIdx.y * 64;

    unsigned long long acc[8][2];
#pragma unroll
    for (int i = 0; i < 8; ++i) { acc[i][0] = 0; acc[i][1] = 0; }

    for (int k0 = 0; k0 < K; k0 += 16) {
#pragma unroll
        for (int j = 0; j < 2; ++j) {
            int i  = tid + (j << 8);
            int lr = i >> 2;
            int lk = (i & 3) << 2;
            float4 v = *reinterpret_cast<const float4*>(&A[(size_t)(m0 + lr) * K + k0 + lk]);
            As[lk + 0][lr] = v.x; As[lk + 1][lr] = v.y;
            As[lk + 2][lr] = v.z; As[lk + 3][lr] = v.w;
        }
        {
            int ln = tid >> 2;
            int lk = (tid & 3) << 2;
            float4 v = *reinterpret_cast<const float4*>(&W[(size_t)(n0 + ln) * K + k0 + lk]);
            Wt[lk + 0][ln] = v.x; Wt[lk + 1][ln] = v.y;
            Wt[lk + 2][ln] = v.z; Wt[lk + 3][ln] = v.w;
        }
        __syncthreads();
#pragma unroll
        for (int kk = 0; kk < 16; ++kk) {
            float4 x0 = *reinterpret_cast<const float4*>(&As[kk][ty << 3]);
            float4 x1 = *reinterpret_cast<const float4*>(&As[kk][(ty << 3) + 4]);
            const ulonglong2 w = *reinterpret_cast<const ulonglong2*>(&Wt[kk][tx << 2]);
            unsigned long long d;
#define GEMM_ROW(i, av, C)                                                     \
            d = pack2(av.C, av.C);                                             \
            acc[i][0] = ffma2(d, w.x, acc[i][0]);                              \
            acc[i][1] = ffma2(d, w.y, acc[i][1]);
            GEMM_ROW(0, x0, x) GEMM_ROW(1, x0, y) GEMM_ROW(2, x0, z) GEMM_ROW(3, x0, w)
            GEMM_ROW(4, x1, x) GEMM_ROW(5, x1, y) GEMM_ROW(6, x1, z) GEMM_ROW(7, x1, w)
#undef GEMM_ROW
        }
        __syncthreads();
    }

    const int n = n0 + (tx << 2);
    unsigned long long bb0 = pack2(b1[n + 0] + b2[n + 0], b1[n + 1] + b2[n + 1]);
    unsigned long long bb1 = pack2(b1[n + 2] + b2[n + 2], b1[n + 3] + b2[n + 3]);
#pragma unroll
    for (int i = 0; i < 8; ++i) {
        int m = m0 + (ty << 3) + i;
        *reinterpret_cast<ulonglong2*>(&C[(size_t)m * N + n]) =
            make_ulonglong2(fadd2(acc[i][0], bb0), fadd2(acc[i][1], bb1));
    }
}

// ---------------------------------------------------------------------------
// logits = h_last @ W_out^T + b_out; out = log_softmax(logits)
// ---------------------------------------------------------------------------
__global__ __launch_bounds__(256) void out_kernel(
    const float* __restrict__ h, const float* __restrict__ Wout,
    const float* __restrict__ bout, float* __restrict__ out)
{
    __shared__ float hs[H_];
    __shared__ float logits[C_];
    __shared__ float red[8];
    int b = blockIdx.x;
    int tid = threadIdx.x;
    int warp = tid >> 5, lane = tid & 31;

    for (int k = tid; k < H_; k += 256) hs[k] = h[(size_t)b * H_ + k];
    __syncthreads();

    for (int c = warp; c < C_; c += 8) {
        const float* wr = Wout + (size_t)c * H_;
        float s = 0.f;
#pragma unroll
        for (int k = lane; k < H_; k += 32) s += hs[k] * wr[k];
#pragma unroll
        for (int off = 16; off > 0; off >>= 1) s += __shfl_down_sync(0xffffffffu, s, off);
        if (lane == 0) logits[c] = s + bout[c];
    }
    __syncthreads();

    float mx = -1e30f;
    for (int c = tid; c < C_; c += 256) mx = fmaxf(mx, logits[c]);
#pragma unroll
    for (int off = 16; off > 0; off >>= 1) mx = fmaxf(mx, __shfl_down_sync(0xffffffffu, mx, off));
    if (lane == 0) red[warp] = mx;
    __syncthreads();
    if (tid == 0) {
        float m2 = red[0];
        for (int i = 1; i < 8; i++) m2 = fmaxf(m2, red[i]);
        red[0] = m2;
    }
    __syncthreads();
    mx = red[0];
    __syncthreads();

    float se = 0.f;
    for (int c = tid; c < C_; c += 256) se += expf(logits[c] - mx);
#pragma unroll
    for (int off = 16; off > 0; off >>= 1) se += __shfl_down_sync(0xffffffffu, se, off);
    if (lane == 0) red[warp] = se;
    __syncthreads();
    if (tid == 0) {
        float s2 = 0.f;
        for (int i = 0; i < 8; i++) s2 += red[i];
        red[0] = logf(s2);
    }
    __syncthreads();
    float lse = red[0];

    for (int c = tid; c < C_; c += 256)
        out[(size_t)b * C_ + c] = logits[c] - mx - lse;
}

static void launch_rnn(const float* xp, const float* Wh,
                       float* hA, float* hB, float* seqOut)
{
    cudaLaunchConfig_t cfg = {};
    cfg.gridDim  = dim3(16, 8, 1);
    cfg.blockDim = dim3(256, 1, 1);
    cfg.dynamicSmemBytes = SMEM_RNN;
    cfg.stream = 0;
    cudaLaunchAttribute attr[1];
    attr[0].id = cudaLaunchAttributeClusterDimension;
    attr[0].val.clusterDim.x = 1;
    attr[0].val.clusterDim.y = 8;
    attr[0].val.clusterDim.z = 1;
    cfg.attrs = attr;
    cfg.numAttrs = 1;
    cudaLaunchKernelEx(&cfg, rnn_layer_kernel, xp, Wh, hA, hB, seqOut);
}

extern "C" void kernel_launch(void* const* d_in, const int* in_sizes, int n_in,
                              void* d_out, int out_size)
{
    (void)in_sizes; (void)n_in; (void)out_size;
    const float* x     = (const float*)d_in[0];
    const float* W_ih0 = (const float*)d_in[1];
    const float* W_hh0 = (const float*)d_in[2];
    const float* b_ih0 = (const float*)d_in[3];
    const float* b_hh0 = (const float*)d_in[4];
    const float* W_ih1 = (const float*)d_in[5];
    const float* W_hh1 = (const float*)d_in[6];
    const float* b_ih1 = (const float*)d_in[7];
    const float* b_hh1 = (const float*)d_in[8];
    const float* W_out = (const float*)d_in[9];
    const float* b_out = (const float*)d_in[10];
    float* out = (float*)d_out;

    float *xp, *seq, *hbuf;
    cudaGetSymbolAddress((void**)&xp,   g_xp);
    cudaGetSymbolAddress((void**)&seq,  g_seq);
    cudaGetSymbolAddress((void**)&hbuf, g_h);
    float* hA = hbuf;
    float* hB = hbuf + B_ * H_;

    cudaFuncSetAttribute(rnn_layer_kernel,
                         cudaFuncAttributeMaxDynamicSharedMemorySize, SMEM_RNN);

    dim3 gg(B_ * S_ / 128, H_ / 64);  // (512, 8)

    // layer 0
    sgemm_bias<<<gg, 256>>>(x, W_ih0, b_ih0, b_hh0, xp, B_ * S_, H_, IN_);
    launch_rnn(xp, W_hh0, hA, hB, seq);

    // layer 1
    sgemm_bias<<<gg, 256>>>(seq, W_ih1, b_ih1, b_hh1, xp, B_ * S_, H_, H_);
    launch_rnn(xp, W_hh1, hA, hB, nullptr);

    // output head on h_{S-1} (t=511 odd -> final state in hB)
    out_kernel<<<B_, 256>>>(hB, W_out, b_out, out);
}

// round 10
// speedup vs baseline: 1.3238x; 1.3238x over previous
#include <cuda_runtime.h>
#include <math.h>

#define B_   128
#define S_   512
#define IN_  128
#define H_   512
#define C_   1000
#define NBLK 128          // persistent grid: 8 x 16 blocks, 1 per SM
#define HP   68           // per-warp Hs row pitch (floats), 16B-aligned

// Scratch (device globals: allocation-free per harness rules)
__device__ float g_xp [(size_t)B_ * S_ * H_];   // input projection (both layers)
__device__ float g_seq[(size_t)B_ * S_ * H_];   // layer-0 hidden sequence
__device__ float g_h  [2 * B_ * H_];            // double-buffered hidden state
__device__ unsigned g_arr2[8];                  // per-m-group arrival counters
__device__ unsigned g_ep2[8];                   // per-m-group epochs (monotonic)

// ---------------- packed fp32x2 helpers (SASS FFMA2 path) -------------------
__device__ __forceinline__ unsigned long long pack2(float lo, float hi) {
    unsigned long long d;
    asm("mov.b64 %0, {%1, %2};" : "=l"(d)
        : "r"(__float_as_uint(lo)), "r"(__float_as_uint(hi)));
    return d;
}
__device__ __forceinline__ unsigned long long ffma2(
    unsigned long long a, unsigned long long b, unsigned long long c) {
    unsigned long long d;
    asm("fma.rn.f32x2 %0, %1, %2, %3;" : "=l"(d) : "l"(a), "l"(b), "l"(c));
    return d;
}
__device__ __forceinline__ unsigned long long fadd2(
    unsigned long long a, unsigned long long b) {
    unsigned long long d;
    asm("add.rn.f32x2 %0, %1, %2;" : "=l"(d) : "l"(a), "l"(b));
    return d;
}
__device__ __forceinline__ float2 unpack2(unsigned long long v) {
    unsigned lo, hi;
    asm("mov.b64 {%0, %1}, %2;" : "=r"(lo), "=r"(hi) : "l"(v));
    return make_float2(__uint_as_float(lo), __uint_as_float(hi));
}

// ---------------------------------------------------------------------------
// 16-block group barrier (blocks sharing blockIdx.x = m-group).
// Monotonic epoch, replay-safe. Fences are scoped (gpu) release/acquire,
// issued by thread 0 ONLY — never a block-wide __threadfence (which emits a
// full L1D flush per thread on sm_103a).
// ---------------------------------------------------------------------------
__device__ __forceinline__ void barrier16(int grp, unsigned base, unsigned step) {
    __syncthreads();    // all block stores happen-before thread 0's fence
    if (threadIdx.x == 0) {
        asm volatile("fence.release.gpu;" ::: "memory");
        unsigned old = atomicAdd(&g_arr2[grp], 1u);
        if (old == 15u) {
            atomicExch(&g_arr2[grp], 0u);          // reset before release
            asm volatile("fence.release.gpu;" ::: "memory");
            atomicAdd(&g_ep2[grp], 1u);            // release epoch
        } else {
            unsigned cur;
            do {
                asm volatile("ld.acquire.gpu.u32 %0, [%1];"
                             : "=r"(cur) : "l"(&g_ep2[grp]));
            } while (cur - base < step);
        }
    }
    __syncthreads();    // broadcast acquire to the whole block
}

// ---------------------------------------------------------------------------
// Persistent RNN layer: 512 steps of Hn[128,512] = tanh(XP[:,t,:] + Hp@Whh^T)
// Grid (8,16) = 128 blocks, 256 threads (8 warps). Block tile 16 rows x 32 cols.
// Whh tile [512][32] resident in smem all layer. Warp g owns k-slice
// [64g, 64g+64): stages its own 16x64 Hs region (syncwarp only), computes a
// 4x4 microtile per thread with packed f32x2 FMAs, dumps packed partials,
// block-reduces 8-way, tanh-stores.
// ---------------------------------------------------------------------------
__global__ void __launch_bounds__(256, 1) rnn_layer_kernel(
    const float* __restrict__ xp, const float* __restrict__ Wh,
    float* __restrict__ hA, float* __restrict__ hB,
    float* __restrict__ seqOut)
{
    extern __shared__ float sm[];
    float* Ws = sm;                     // [512][32] k-major        (64 KB)
    float* Hs = Ws + 512 * 32;          // 8 x [16][HP] per-warp    (34 KB)
    float* Pr = Hs + 8 * 16 * HP;       // [8][512] packed partials (16 KB)
    __shared__ unsigned s_base;

    const int tid  = threadIdx.x;
    const int bx   = blockIdx.x;
    const int m0   = bx << 4;            // 8 m-groups  -> 128 rows
    const int n0   = blockIdx.y << 5;    // 16 n-groups -> 512 cols
    const int g    = tid >> 5;           // warp = K-group 0..7
    const int lane = tid & 31;
    const int r0   = (lane >> 3) << 2;   // rows r0..r0+3
    const int c0   = (lane & 7) << 2;    // cols c0..c0+3
    float* HsW = Hs + g * (16 * HP);

    if (tid == 0) {
        unsigned cur;
        asm volatile("ld.acquire.gpu.u32 %0, [%1];" : "=r"(cur) : "l"(&g_ep2[bx]));
        s_base = cur;
    }

    // Load Whh tile once: Ws[k][n], n in [n0, n0+32), k in [0,512)
    for (int i = tid; i < 32 * 128; i += 256) {
        int n  = i & 31;
        int k4 = i >> 5;
        float4 v = *reinterpret_cast<const float4*>(
            &Wh[(size_t)(n0 + n) * H_ + (k4 << 2)]);
        int k = k4 << 2;
        Ws[(k + 0) * 32 + n] = v.x;
        Ws[(k + 1) * 32 + n] = v.y;
        Ws[(k + 2) * 32 + n] = v.z;
        Ws[(k + 3) * 32 + n] = v.w;
    }
    __syncthreads();
    const unsigned base = s_base;

    // Epilogue: thread owns 2 adjacent outputs (one f32x2)
    const int i0 = tid << 1;
    const int er = tid >> 4;             // 0..15
    const int ec = i0 & 31;              // even 0..30
    const int kbeg = g << 6;

    const float* xptr = xp + ((size_t)(m0 + er) * S_) * H_ + n0 + ec;
    float2 xv = __ldg(reinterpret_cast<const float2*>(xptr));   // t = 0

    for (int t = 0; t < S_; ++t) {
        const float* hp = (t & 1) ? hA : hB;
        float*       hn = (t & 1) ? hB : hA;

        float s0 = 0.f, s1 = 0.f;

        if (t > 0) {
            // Per-warp staging of own k-slice (16 rows x 64 k)
#pragma unroll
            for (int j = 0; j < 8; ++j) {
                int idx = lane + (j << 5);
                int r = idx >> 4, k4 = idx & 15;
                float4 v = __ldcg(reinterpret_cast<const float4*>(
                    &hp[(size_t)(m0 + r) * H_ + kbeg + (k4 << 2)]));
                *reinterpret_cast<float4*>(&HsW[r * HP + (k4 << 2)]) = v;
            }
            __syncwarp();

            unsigned long long a00 = 0, a01 = 0, a10 = 0, a11 = 0;
            unsigned long long a20 = 0, a21 = 0, a30 = 0, a31 = 0;

#pragma unroll 4
            for (int k4i = 0; k4i < 16; ++k4i) {
                const int kk = k4i << 2;
                float4 h0 = *reinterpret_cast<const float4*>(&HsW[(r0 + 0) * HP + kk]);
                float4 h1 = *reinterpret_cast<const float4*>(&HsW[(r0 + 1) * HP + kk]);
                float4 h2 = *reinterpret_cast<const float4*>(&HsW[(r0 + 2) * HP + kk]);
                float4 h3 = *reinterpret_cast<const float4*>(&HsW[(r0 + 3) * HP + kk]);
#define RNN_SUBK(s, C)                                                         \
                {                                                              \
                    const ulonglong2 w = *reinterpret_cast<const ulonglong2*>( \
                        &Ws[(kbeg + kk + s) * 32 + c0]);                       \
                    unsigned long long d;                                      \
                    d = pack2(h0.C, h0.C);                                     \
                    a00 = ffma2(d, w.x, a00); a01 = ffma2(d, w.y, a01);        \
                    d = pack2(h1.C, h1.C);                                     \
                    a10 = ffma2(d, w.x, a10); a11 = ffma2(d, w.y, a11);        \
                    d = pack2(h2.C, h2.C);                                     \
                    a20 = ffma2(d, w.x, a20); a21 = ffma2(d, w.y, a21);        \
                    d = pack2(h3.C, h3.C);                                     \
                    a30 = ffma2(d, w.x, a30); a31 = ffma2(d, w.y, a31);        \
                }
                RNN_SUBK(0, x)
                RNN_SUBK(1, y)
                RNN_SUBK(2, z)
                RNN_SUBK(3, w)
#undef RNN_SUBK
            }

            // Packed partials: Pr[g][row][col-pair] (bit-identical to floats)
            float* pg = &Pr[g << 9];
            *reinterpret_cast<ulonglong2*>(&pg[(r0 + 0) * 32 + c0]) = make_ulonglong2(a00, a01);
            *reinterpret_cast<ulonglong2*>(&pg[(r0 + 1) * 32 + c0]) = make_ulonglong2(a10, a11);
            *reinterpret_cast<ulonglong2*>(&pg[(r0 + 2) * 32 + c0]) = make_ulonglong2(a20, a21);
            *reinterpret_cast<ulonglong2*>(&pg[(r0 + 3) * 32 + c0]) = make_ulonglong2(a30, a31);
            __syncthreads();

            unsigned long long sp = 0;
#pragma unroll
            for (int gg = 0; gg < 8; ++gg)
                sp = fadd2(sp, *reinterpret_cast<const unsigned long long*>(
                                   &Pr[(gg << 9) + i0]));
            float2 sf = unpack2(sp);
            s0 = sf.x; s1 = sf.y;
            // Pr reuse next step is safe: reduce-loads precede the group
            // barrier below; next step's stores come after it.
        }
        // t == 0: h_{-1}=0 -> output = tanh(xp)

        float2 o;
        o.x = tanhf(s0 + xv.x);
        o.y = tanhf(s1 + xv.y);
        __stcg(reinterpret_cast<float2*>(&hn[(size_t)(m0 + er) * H_ + n0 + ec]), o);
        if (seqOut)
            __stcg(reinterpret_cast<float2*>(
                &seqOut[((size_t)(m0 + er) * S_ + t) * H_ + n0 + ec]), o);

        if (t != S_ - 1) {
            // Prefetch next step's xp (independent; hides under barrier skew)
            xv = __ldg(reinterpret_cast<const float2*>(xptr + (size_t)(t + 1) * H_));
            barrier16(bx, base, (unsigned)(t + 1));
        }
    }
}

// ---------------------------------------------------------------------------
// C[M,N] = A[M,K] @ W[N,K]^T + b1[N] + b2[N]
// 128x64 tile, BK=16, 256 threads, 8x4 microtile, packed f32x2 FMAs.
// ---------------------------------------------------------------------------
__global__ __launch_bounds__(256) void sgemm_bias(
    const float* __restrict__ A, const float* __restrict__ W,
    const float* __restrict__ b1, const float* __restrict__ b2,
    float* __restrict__ C, int M, int N, int K)
{
    __shared__ float As[16][132];
    __shared__ float Wt[16][68];
    const int tid = threadIdx.x;
    const int tx = tid & 15, ty = tid >> 4;
    const int m0 = blockIdx.x * 128, n0 = blockIdx.y * 64;

    unsigned long long acc[8][2];
#pragma unroll
    for (int i = 0; i < 8; ++i) { acc[i][0] = 0; acc[i][1] = 0; }

    for (int k0 = 0; k0 < K; k0 += 16) {
#pragma unroll
        for (int j = 0; j < 2; ++j) {
            int i  = tid + (j << 8);
            int lr = i >> 2;
            int lk = (i & 3) << 2;
            float4 v = *reinterpret_cast<const float4*>(&A[(size_t)(m0 + lr) * K + k0 + lk]);
            As[lk + 0][lr] = v.x; As[lk + 1][lr] = v.y;
            As[lk + 2][lr] = v.z; As[lk + 3][lr] = v.w;
        }
        {
            int ln = tid >> 2;
            int lk = (tid & 3) << 2;
            float4 v = *reinterpret_cast<const float4*>(&W[(size_t)(n0 + ln) * K + k0 + lk]);
            Wt[lk + 0][ln] = v.x; Wt[lk + 1][ln] = v.y;
            Wt[lk + 2][ln] = v.z; Wt[lk + 3][ln] = v.w;
        }
        __syncthreads();
#pragma unroll
        for (int kk = 0; kk < 16; ++kk) {
            float4 x0 = *reinterpret_cast<const float4*>(&As[kk][ty << 3]);
            float4 x1 = *reinterpret_cast<const float4*>(&As[kk][(ty << 3) + 4]);
            const ulonglong2 w = *reinterpret_cast<const ulonglong2*>(&Wt[kk][tx << 2]);
            unsigned long long d;
#define GEMM_ROW(i, av, C)                                                     \
            d = pack2(av.C, av.C);                                             \
            acc[i][0] = ffma2(d, w.x, acc[i][0]);                              \
            acc[i][1] = ffma2(d, w.y, acc[i][1]);
            GEMM_ROW(0, x0, x) GEMM_ROW(1, x0, y) GEMM_ROW(2, x0, z) GEMM_ROW(3, x0, w)
            GEMM_ROW(4, x1, x) GEMM_ROW(5, x1, y) GEMM_ROW(6, x1, z) GEMM_ROW(7, x1, w)
#undef GEMM_ROW
        }
        __syncthreads();
    }

    const int n = n0 + (tx << 2);
    unsigned long long bb0 = pack2(b1[n + 0] + b2[n + 0], b1[n + 1] + b2[n + 1]);
    unsigned long long bb1 = pack2(b1[n + 2] + b2[n + 2], b1[n + 3] + b2[n + 3]);
#pragma unroll
    for (int i = 0; i < 8; ++i) {
        int m = m0 + (ty << 3) + i;
        *reinterpret_cast<ulonglong2*>(&C[(size_t)m * N + n]) =
            make_ulonglong2(fadd2(acc[i][0], bb0), fadd2(acc[i][1], bb1));
    }
}

// ---------------------------------------------------------------------------
// logits = h_last @ W_out^T + b_out; out = log_softmax(logits)
// ---------------------------------------------------------------------------
__global__ __launch_bounds__(256) void out_kernel(
    const float* __restrict__ h, const float* __restrict__ Wout,
    const float* __restrict__ bout, float* __restrict__ out)
{
    __shared__ float hs[H_];
    __shared__ float logits[C_];
    __shared__ float red[8];
    int b = blockIdx.x;
    int tid = threadIdx.x;
    int warp = tid >> 5, lane = tid & 31;

    for (int k = tid; k < H_; k += 256) hs[k] = h[(size_t)b * H_ + k];
    __syncthreads();

    for (int c = warp; c < C_; c += 8) {
        const float* wr = Wout + (size_t)c * H_;
        float s = 0.f;
#pragma unroll
        for (int k = lane; k < H_; k += 32) s += hs[k] * wr[k];
#pragma unroll
        for (int off = 16; off > 0; off >>= 1) s += __shfl_down_sync(0xffffffffu, s, off);
        if (lane == 0) logits[c] = s + bout[c];
    }
    __syncthreads();

    float mx = -1e30f;
    for (int c = tid; c < C_; c += 256) mx = fmaxf(mx, logits[c]);
#pragma unroll
    for (int off = 16; off > 0; off >>= 1) mx = fmaxf(mx, __shfl_down_sync(0xffffffffu, mx, off));
    if (lane == 0) red[warp] = mx;
    __syncthreads();
    if (tid == 0) {
        float m2 = red[0];
        for (int i = 1; i < 8; i++) m2 = fmaxf(m2, red[i]);
        red[0] = m2;
    }
    __syncthreads();
    mx = red[0];
    __syncthreads();

    float se = 0.f;
    for (int c = tid; c < C_; c += 256) se += expf(logits[c] - mx);
#pragma unroll
    for (int off = 16; off > 0; off >>= 1) se += __shfl_down_sync(0xffffffffu, se, off);
    if (lane == 0) red[warp] = se;
    __syncthreads();
    if (tid == 0) {
        float s2 = 0.f;
        for (int i = 0; i < 8; i++) s2 += red[i];
        red[0] = logf(s2);
    }
    __syncthreads();
    float lse = red[0];

    for (int c = tid; c < C_; c += 256)
        out[(size_t)b * C_ + c] = logits[c] - mx - lse;
}

extern "C" void kernel_launch(void* const* d_in, const int* in_sizes, int n_in,
                              void* d_out, int out_size)
{
    (void)in_sizes; (void)n_in; (void)out_size;
    const float* x     = (const float*)d_in[0];
    const float* W_ih0 = (const float*)d_in[1];
    const float* W_hh0 = (const float*)d_in[2];
    const float* b_ih0 = (const float*)d_in[3];
    const float* b_hh0 = (const float*)d_in[4];
    const float* W_ih1 = (const float*)d_in[5];
    const float* W_hh1 = (const float*)d_in[6];
    const float* b_ih1 = (const float*)d_in[7];
    const float* b_hh1 = (const float*)d_in[8];
    const float* W_out = (const float*)d_in[9];
    const float* b_out = (const float*)d_in[10];
    float* out = (float*)d_out;

    float *xp, *seq, *hbuf;
    cudaGetSymbolAddress((void**)&xp,   g_xp);
    cudaGetSymbolAddress((void**)&seq,  g_seq);
    cudaGetSymbolAddress((void**)&hbuf, g_h);
    float* hA = hbuf;
    float* hB = hbuf + B_ * H_;

    const int smem_bytes = (512 * 32 + 8 * 16 * HP + 8 * 512) * 4;  // 116736
    cudaFuncSetAttribute(rnn_layer_kernel,
                         cudaFuncAttributeMaxDynamicSharedMemorySize, smem_bytes);

    dim3 gg(B_ * S_ / 128, H_ / 64);  // (512, 8)
    dim3 gr(B_ / 16, H_ / 32);        // (8, 16) = 128 persistent blocks

    // layer 0
    sgemm_bias<<<gg, 256>>>(x, W_ih0, b_ih0, b_hh0, xp, B_ * S_, H_, IN_);
    rnn_layer_kernel<<<gr, 256, smem_bytes>>>(xp, W_hh0, hA, hB, seq);

    // layer 1
    sgemm_bias<<<gg, 256>>>(seq, W_ih1, b_ih1, b_hh1, xp, B_ * S_, H_, H_);
    rnn_layer_kernel<<<gr, 256, smem_bytes>>>(xp, W_hh1, hA, hB, nullptr);

    // output head on h_{S-1} (t=511 odd -> final state in hB)
    out_kernel<<<B_, 256>>>(hB, W_out, b_out, out);
}

// round 11
// speedup vs baseline: 1.5088x; 1.1398x over previous
#include <cuda_runtime.h>
#include <math.h>

#define B_   128
#define S_   512
#define IN_  128
#define H_   512
#define C_   1000
#define NWRP 16           // warps per rnn block
#define HSPW 36           // per-warp Hs row pitch (floats), 16B-aligned

// Scratch (device globals: allocation-free per harness rules)
__device__ float g_xp [(size_t)B_ * S_ * H_];   // input projection (both layers)
__device__ float g_seq[(size_t)B_ * S_ * H_];   // layer-0 hidden sequence
__device__ float g_h  [2 * B_ * H_];            // double-buffered hidden state
__device__ unsigned g_flags[128];               // per-block step flags (monotonic)

// ---------------- packed fp32x2 helpers (SASS FFMA2 path) -------------------
__device__ __forceinline__ unsigned long long pack2(float lo, float hi) {
    unsigned long long d;
    asm("mov.b64 %0, {%1, %2};" : "=l"(d)
        : "r"(__float_as_uint(lo)), "r"(__float_as_uint(hi)));
    return d;
}
__device__ __forceinline__ unsigned long long ffma2(
    unsigned long long a, unsigned long long b, unsigned long long c) {
    unsigned long long d;
    asm("fma.rn.f32x2 %0, %1, %2, %3;" : "=l"(d) : "l"(a), "l"(b), "l"(c));
    return d;
}
__device__ __forceinline__ unsigned long long fadd2(
    unsigned long long a, unsigned long long b) {
    unsigned long long d;
    asm("add.rn.f32x2 %0, %1, %2;" : "=l"(d) : "l"(a), "l"(b));
    return d;
}

// ---------------------------------------------------------------------------
// Persistent RNN layer, fine-grained producer->consumer flags.
// Grid (8,16) = 128 blocks, 512 threads (16 warps). Block tile: 16 rows
// (m0 = bx*16) x 32 cols (n0 = by*32). Whh tile [512][32] resident in smem.
// Warp g consumes h k-slice [32g, 32g+32), produced by block (bx, by=g):
// it spin-waits (acquire) on that ONE block's flag, stages its slice, and
// runs a 4x4 f32x2 microtile. Partials (16-way K-split) reduced via smem.
// A block releases its own flag after its h stores each step. Flags are
// monotonic (+512 per launch, uniform) -> replay-safe; base is the block's
// own flag at launch (all flags equal at launch start).
// ---------------------------------------------------------------------------
__global__ void __launch_bounds__(512, 1) rnn_layer_kernel(
    const float* __restrict__ xp, const float* __restrict__ Wh,
    float* __restrict__ hA, float* __restrict__ hB,
    float* __restrict__ seqOut)
{
    extern __shared__ float sm[];
    float* Ws = sm;                       // [512][32] k-major       (64 KB)
    float* Hs = Ws + 512 * 32;            // 16 x [16][HSPW] per-warp(36 KB)
    float* Pr = Hs + NWRP * 16 * HSPW;    // [16][512] partials      (32 KB)
    __shared__ unsigned s_base;

    const int tid  = threadIdx.x;
    const int bx   = blockIdx.x;
    const int by   = blockIdx.y;
    const int m0   = bx << 4;             // 8 m-groups  -> 128 rows
    const int n0   = by << 5;             // 16 n-groups -> 512 cols
    const int g    = tid >> 5;            // warp = K-group 0..15
    const int lane = tid & 31;
    const int r0   = (lane >> 3) << 2;    // rows r0..r0+3
    const int c0   = (lane & 7) << 2;     // cols c0..c0+3
    const int kbeg = g << 5;              // 32 k per warp
    const int fi   = (bx << 4) + by;      // own flag index
    const int pfi  = (bx << 4) + g;       // producer flag for this warp
    float* HsW = Hs + g * (16 * HSPW);

    if (tid == 0) {
        unsigned cur;   // own flag: race-free base (only we increment it)
        asm volatile("ld.acquire.gpu.u32 %0, [%1];" : "=r"(cur) : "l"(&g_flags[fi]));
        s_base = cur;
    }

    // Load Whh tile once: Ws[k][n], n in [n0, n0+32), k in [0,512)
    for (int i = tid; i < 32 * 128; i += 512) {
        int n  = i & 31;
        int k4 = i >> 5;
        float4 v = *reinterpret_cast<const float4*>(
            &Wh[(size_t)(n0 + n) * H_ + (k4 << 2)]);
        int k = k4 << 2;
        Ws[(k + 0) * 32 + n] = v.x;
        Ws[(k + 1) * 32 + n] = v.y;
        Ws[(k + 2) * 32 + n] = v.z;
        Ws[(k + 3) * 32 + n] = v.w;
    }
    __syncthreads();
    const unsigned base = s_base;

    // Epilogue: thread owns 1 output (scalar, coalesced per warp-row)
    const int er = tid >> 5;              // 0..15 (== g)
    const int ec = tid & 31;              // 0..31

    const float* xrow = xp + ((size_t)(m0 + er) * S_) * H_ + n0 + ec;
    float xv = __ldg(xrow);               // t = 0

    for (int t = 0; t < S_; ++t) {
        const float* hp = (t & 1) ? hA : hB;
        float*       hn = (t & 1) ? hB : hA;

        float s = 0.f;

        if (t > 0) {
            // Wait for THIS warp's single producer block (acquire).
            if (lane == 0) {
                unsigned cur;
                do {
                    asm volatile("ld.acquire.gpu.u32 %0, [%1];"
                                 : "=r"(cur) : "l"(&g_flags[pfi]));
                } while (cur - base < (unsigned)t);
            }
            __syncwarp();

            // Stage own k-slice: 16 rows x 32 k (warp-private region)
#pragma unroll
            for (int j = 0; j < 4; ++j) {
                int idx = lane + (j << 5);
                int r = idx >> 3, k4 = idx & 7;
                float4 v = __ldcg(reinterpret_cast<const float4*>(
                    &hp[(size_t)(m0 + r) * H_ + kbeg + (k4 << 2)]));
                *reinterpret_cast<float4*>(&HsW[r * HSPW + (k4 << 2)]) = v;
            }
            __syncwarp();

            unsigned long long a00 = 0, a01 = 0, a10 = 0, a11 = 0;
            unsigned long long a20 = 0, a21 = 0, a30 = 0, a31 = 0;

#pragma unroll
            for (int k4i = 0; k4i < 8; ++k4i) {
                const int kk = k4i << 2;
                float4 h0 = *reinterpret_cast<const float4*>(&HsW[(r0 + 0) * HSPW + kk]);
                float4 h1 = *reinterpret_cast<const float4*>(&HsW[(r0 + 1) * HSPW + kk]);
                float4 h2 = *reinterpret_cast<const float4*>(&HsW[(r0 + 2) * HSPW + kk]);
                float4 h3 = *reinterpret_cast<const float4*>(&HsW[(r0 + 3) * HSPW + kk]);
#define RNN_SUBK(ss, C)                                                        \
                {                                                              \
                    const ulonglong2 w = *reinterpret_cast<const ulonglong2*>( \
                        &Ws[(kbeg + kk + ss) * 32 + c0]);                      \
                    unsigned long long d;                                      \
                    d = pack2(h0.C, h0.C);                                     \
                    a00 = ffma2(d, w.x, a00); a01 = ffma2(d, w.y, a01);        \
                    d = pack2(h1.C, h1.C);                                     \
                    a10 = ffma2(d, w.x, a10); a11 = ffma2(d, w.y, a11);        \
                    d = pack2(h2.C, h2.C);                                     \
                    a20 = ffma2(d, w.x, a20); a21 = ffma2(d, w.y, a21);        \
                    d = pack2(h3.C, h3.C);                                     \
                    a30 = ffma2(d, w.x, a30); a31 = ffma2(d, w.y, a31);        \
                }
                RNN_SUBK(0, x)
                RNN_SUBK(1, y)
                RNN_SUBK(2, z)
                RNN_SUBK(3, w)
#undef RNN_SUBK
            }

            // Partials: Pr[g][row*32 + col]
            float* pg = &Pr[g << 9];
            *reinterpret_cast<ulonglong2*>(&pg[(r0 + 0) * 32 + c0]) = make_ulonglong2(a00, a01);
            *reinterpret_cast<ulonglong2*>(&pg[(r0 + 1) * 32 + c0]) = make_ulonglong2(a10, a11);
            *reinterpret_cast<ulonglong2*>(&pg[(r0 + 2) * 32 + c0]) = make_ulonglong2(a20, a21);
            *reinterpret_cast<ulonglong2*>(&pg[(r0 + 3) * 32 + c0]) = make_ulonglong2(a30, a31);
            __syncthreads();

            // 16-way reduction: thread tid sums Pr[gg][tid]
#pragma unroll
            for (int gg = 0; gg < 16; ++gg)
                s += Pr[(gg << 9) + tid];
        }
        // t == 0: h_{-1}=0 -> output = tanh(xp)

        float o = tanhf(s + xv);
        __stcg(&hn[(size_t)(m0 + er) * H_ + n0 + ec], o);
        if (seqOut)
            __stcg(&seqOut[((size_t)(m0 + er) * S_ + t) * H_ + n0 + ec], o);

        if (t != S_ - 1)   // prefetch next xp (hides under release/poll)
            xv = __ldg(xrow + (size_t)(t + 1) * H_);

        __syncthreads();   // h stores + Pr reads done block-wide
        if (tid == 0) {
            asm volatile("fence.release.gpu;" ::: "memory");
            atomicAdd(&g_flags[fi], 1u);   // publish step t (uniform: +512/launch)
        }
    }
}

// ---------------------------------------------------------------------------
// C[M,N] = A[M,K] @ W[N,K]^T + b1[N] + b2[N]
// 128x64 tile, BK=16, 256 threads, 8x4 microtile, packed f32x2 FMAs.
// ---------------------------------------------------------------------------
__global__ __launch_bounds__(256) void sgemm_bias(
    const float* __restrict__ A, const float* __restrict__ W,
    const float* __restrict__ b1, const float* __restrict__ b2,
    float* __restrict__ C, int M, int N, int K)
{
    __shared__ float As[16][132];
    __shared__ float Wt[16][68];
    const int tid = threadIdx.x;
    const int tx = tid & 15, ty = tid >> 4;
    const int m0 = blockIdx.x * 128, n0 = blockIdx.y * 64;

    unsigned long long acc[8][2];
#pragma unroll
    for (int i = 0; i < 8; ++i) { acc[i][0] = 0; acc[i][1] = 0; }

    for (int k0 = 0; k0 < K; k0 += 16) {
#pragma unroll
        for (int j = 0; j < 2; ++j) {
            int i  = tid + (j << 8);
            int lr = i >> 2;
            int lk = (i & 3) << 2;
            float4 v = *reinterpret_cast<const float4*>(&A[(size_t)(m0 + lr) * K + k0 + lk]);
            As[lk + 0][lr] = v.x; As[lk + 1][lr] = v.y;
            As[lk + 2][lr] = v.z; As[lk + 3][lr] = v.w;
        }
        {
            int ln = tid >> 2;
            int lk = (tid & 3) << 2;
            float4 v = *reinterpret_cast<const float4*>(&W[(size_t)(n0 + ln) * K + k0 + lk]);
            Wt[lk + 0][ln] = v.x; Wt[lk + 1][ln] = v.y;
            Wt[lk + 2][ln] = v.z; Wt[lk + 3][ln] = v.w;
        }
        __syncthreads();
#pragma unroll
        for (int kk = 0; kk < 16; ++kk) {
            float4 x0 = *reinterpret_cast<const float4*>(&As[kk][ty << 3]);
            float4 x1 = *reinterpret_cast<const float4*>(&As[kk][(ty << 3) + 4]);
            const ulonglong2 w = *reinterpret_cast<const ulonglong2*>(&Wt[kk][tx << 2]);
            unsigned long long d;
#define GEMM_ROW(i, av, C)                                                     \
            d = pack2(av.C, av.C);                                             \
            acc[i][0] = ffma2(d, w.x, acc[i][0]);                              \
            acc[i][1] = ffma2(d, w.y, acc[i][1]);
            GEMM_ROW(0, x0, x) GEMM_ROW(1, x0, y) GEMM_ROW(2, x0, z) GEMM_ROW(3, x0, w)
            GEMM_ROW(4, x1, x) GEMM_ROW(5, x1, y) GEMM_ROW(6, x1, z) GEMM_ROW(7, x1, w)
#undef GEMM_ROW
        }
        __syncthreads();
    }

    const int n = n0 + (tx << 2);
    unsigned long long bb0 = pack2(b1[n + 0] + b2[n + 0], b1[n + 1] + b2[n + 1]);
    unsigned long long bb1 = pack2(b1[n + 2] + b2[n + 2], b1[n + 3] + b2[n + 3]);
#pragma unroll
    for (int i = 0; i < 8; ++i) {
        int m = m0 + (ty << 3) + i;
        *reinterpret_cast<ulonglong2*>(&C[(size_t)m * N + n]) =
            make_ulonglong2(fadd2(acc[i][0], bb0), fadd2(acc[i][1], bb1));
    }
}

// ---------------------------------------------------------------------------
// logits = h_last @ W_out^T + b_out; out = log_softmax(logits)
// ---------------------------------------------------------------------------
__global__ __launch_bounds__(256) void out_kernel(
    const float* __restrict__ h, const float* __restrict__ Wout,
    const float* __restrict__ bout, float* __restrict__ out)
{
    __shared__ float hs[H_];
    __shared__ float logits[C_];
    __shared__ float red[8];
    int b = blockIdx.x;
    int tid = threadIdx.x;
    int warp = tid >> 5, lane = tid & 31;

    for (int k = tid; k < H_; k += 256) hs[k] = h[(size_t)b * H_ + k];
    __syncthreads();

    for (int c = warp; c < C_; c += 8) {
        const float* wr = Wout + (size_t)c * H_;
        float s = 0.f;
#pragma unroll
        for (int k = lane; k < H_; k += 32) s += hs[k] * wr[k];
#pragma unroll
        for (int off = 16; off > 0; off >>= 1) s += __shfl_down_sync(0xffffffffu, s, off);
        if (lane == 0) logits[c] = s + bout[c];
    }
    __syncthreads();

    float mx = -1e30f;
    for (int c = tid; c < C_; c += 256) mx = fmaxf(mx, logits[c]);
#pragma unroll
    for (int off = 16; off > 0; off >>= 1) mx = fmaxf(mx, __shfl_down_sync(0xffffffffu, mx, off));
    if (lane == 0) red[warp] = mx;
    __syncthreads();
    if (tid == 0) {
        float m2 = red[0];
        for (int i = 1; i < 8; i++) m2 = fmaxf(m2, red[i]);
        red[0] = m2;
    }
    __syncthreads();
    mx = red[0];
    __syncthreads();

    float se = 0.f;
    for (int c = tid; c < C_; c += 256) se += expf(logits[c] - mx);
#pragma unroll
    for (int off = 16; off > 0; off >>= 1) se += __shfl_down_sync(0xffffffffu, se, off);
    if (lane == 0) red[warp] = se;
    __syncthreads();
    if (tid == 0) {
        float s2 = 0.f;
        for (int i = 0; i < 8; i++) s2 += red[i];
        red[0] = logf(s2);
    }
    __syncthreads();
    float lse = red[0];

    for (int c = tid; c < C_; c += 256)
        out[(size_t)b * C_ + c] = logits[c] - mx - lse;
}

extern "C" void kernel_launch(void* const* d_in, const int* in_sizes, int n_in,
                              void* d_out, int out_size)
{
    (void)in_sizes; (void)n_in; (void)out_size;
    const float* x     = (const float*)d_in[0];
    const float* W_ih0 = (const float*)d_in[1];
    const float* W_hh0 = (const float*)d_in[2];
    const float* b_ih0 = (const float*)d_in[3];
    const float* b_hh0 = (const float*)d_in[4];
    const float* W_ih1 = (const float*)d_in[5];
    const float* W_hh1 = (const float*)d_in[6];
    const float* b_ih1 = (const float*)d_in[7];
    const float* b_hh1 = (const float*)d_in[8];
    const float* W_out = (const float*)d_in[9];
    const float* b_out = (const float*)d_in[10];
    float* out = (float*)d_out;

    float *xp, *seq, *hbuf;
    cudaGetSymbolAddress((void**)&xp,   g_xp);
    cudaGetSymbolAddress((void**)&seq,  g_seq);
    cudaGetSymbolAddress((void**)&hbuf, g_h);
    float* hA = hbuf;
    float* hB = hbuf + B_ * H_;

    const int smem_bytes = (512 * 32 + NWRP * 16 * HSPW + NWRP * 512) * 4; // 135168
    cudaFuncSetAttribute(rnn_layer_kernel,
                         cudaFuncAttributeMaxDynamicSharedMemorySize, smem_bytes);

    dim3 gg(B_ * S_ / 128, H_ / 64);  // (512, 8)
    dim3 gr(B_ / 16, H_ / 32);        // (8, 16) = 128 persistent blocks

    // layer 0
    sgemm_bias<<<gg, 256>>>(x, W_ih0, b_ih0, b_hh0, xp, B_ * S_, H_, IN_);
    rnn_layer_kernel<<<gr, 512, smem_bytes>>>(xp, W_hh0, hA, hB, seq);

    // layer 1
    sgemm_bias<<<gg, 256>>>(seq, W_ih1, b_ih1, b_hh1, xp, B_ * S_, H_, H_);
    rnn_layer_kernel<<<gr, 512, smem_bytes>>>(xp, W_hh1, hA, hB, nullptr);

    // output head on h_{S-1} (t=511 odd -> final state in hB)
    out_kernel<<<B_, 256>>>(hB, W_out, b_out, out);
}